// round 4
// baseline (speedup 1.0000x reference)
#include <cuda_runtime.h>

#define V_N   100000
#define E_N   1600000
#define NI    128
#define H     50
#define PW    56          // padded row width: two 16B-aligned 28-col halves
#define HF    28          // cols per half
#define EFW   53          // edge-feature smem stride (odd -> conflict-free scalar reads)
#define EB    512         // edges per tile
#define NTE   512         // k_edge threads
#define NT    256         // node kernel threads

typedef unsigned long long u64;

__device__ float g_left [(size_t)V_N * PW];
__device__ float g_right[(size_t)V_N * PW];
__device__ float g_acc  [(size_t)V_N * PW];

// ---- helpers --------------------------------------------------------------
__device__ __forceinline__ u64 pk2(float x, float y) {
    u64 r; asm("mov.b64 %0, {%1, %2};" : "=l"(r) : "f"(x), "f"(y)); return r;
}
__device__ __forceinline__ float2 up2(u64 v) {
    float2 r; asm("mov.b64 {%0, %1}, %2;" : "=f"(r.x), "=f"(r.y) : "l"(v)); return r;
}
__device__ __forceinline__ u64 ffma2(u64 a, u64 b, u64 c) {
    u64 d; asm("fma.rn.f32x2 %0, %1, %2, %3;" : "=l"(d) : "l"(a), "l"(b), "l"(c)); return d;
}
__device__ __forceinline__ float relu_f(float x) { return fmaxf(x, 0.0f); }

__device__ __forceinline__ void red4(float* p, float a, float b, float c, float d) {
    asm volatile("red.global.add.v4.f32 [%0], {%1,%2,%3,%4};"
                 :: "l"(p), "f"(a), "f"(b), "f"(c), "f"(d) : "memory");
}

// two-row accumulate over one 28-col half: a{0,1}[0..13] += x{0,1} * W[0..27]
// W must be 16B-aligned; 7 LDS.128 feed 28 FFMA2.
__device__ __forceinline__ void acc2(u64* a0, u64* a1, float x0, float x1,
                                     const float* W) {
    u64 xx0 = pk2(x0, x0), xx1 = pk2(x1, x1);
    const ulonglong2* w = reinterpret_cast<const ulonglong2*>(W);
    #pragma unroll
    for (int q = 0; q < 7; q++) {
        ulonglong2 ww = w[q];
        a0[2 * q]     = ffma2(xx0, ww.x, a0[2 * q]);
        a0[2 * q + 1] = ffma2(xx0, ww.y, a0[2 * q + 1]);
        a1[2 * q]     = ffma2(xx1, ww.x, a1[2 * q]);
        a1[2 * q + 1] = ffma2(xx1, ww.y, a1[2 * q + 1]);
    }
}

// stage [rows_real x 50] matrix into [rows_pad x 56] smem, zero pads
__device__ __forceinline__ void stage_w(float* s, const float* g, int rows_real,
                                        int rows_pad, int tid, int nt) {
    int tot = rows_pad * PW;
    for (int i = tid; i < tot; i += nt) {
        int r = i / PW, c = i % PW;
        s[i] = (c < H && r < rows_real) ? g[r * H + c] : 0.0f;
    }
}
__device__ __forceinline__ void stage_b(float* s, const float* g, int tid) {
    if (tid < PW) s[tid] = (tid < H) ? g[tid] : 0.0f;
}

// ---------------------------------------------------------------------------
// Kernel 1: left/right tables (no relu) + zero scatter accumulator
// thread: nodes n0,n1 = consecutive pair, columns [half*28, half*28+28)
// ---------------------------------------------------------------------------
__global__ void __launch_bounds__(NT) k_node_lr(
    const float* __restrict__ nf,
    const float* __restrict__ w_l, const float* __restrict__ b_l,
    const float* __restrict__ w_r, const float* __restrict__ b_r)
{
    extern __shared__ float sm[];
    float* s_wl = sm;                 // 128*56
    float* s_wr = s_wl + NI * PW;     // 128*56
    float* s_bl = s_wr + NI * PW;     // 56
    float* s_br = s_bl + PW;          // 56
    stage_w(s_wl, w_l, NI, NI, threadIdx.x, NT);
    stage_w(s_wr, w_r, NI, NI, threadIdx.x, NT);
    stage_b(s_bl, b_l, threadIdx.x);
    stage_b(s_br, b_r, threadIdx.x);

    {   // zero g_acc
        float4 z = make_float4(0.f, 0.f, 0.f, 0.f);
        size_t tot = (size_t)V_N * PW / 4;
        for (size_t i = (size_t)blockIdx.x * NT + threadIdx.x; i < tot; i += (size_t)gridDim.x * NT)
            reinterpret_cast<float4*>(g_acc)[i] = z;
    }
    __syncthreads();

    const int half = threadIdx.x & 1;
    const int co   = half * HF;
    int n0 = blockIdx.x * NT + 2 * (threadIdx.x >> 1);
    if (n0 >= V_N) return;
    int n1 = n0 + 1;
    const float4* r0 = reinterpret_cast<const float4*>(nf + (size_t)n0 * NI);
    const float4* r1 = reinterpret_cast<const float4*>(nf + (size_t)n1 * NI);

    #pragma unroll 1
    for (int pass = 0; pass < 2; pass++) {
        const float* W = (pass ? s_wr : s_wl) + co;
        const u64*  B2 = reinterpret_cast<const u64*>((pass ? s_br : s_bl) + co);
        u64 a0[14], a1[14];
        #pragma unroll
        for (int q = 0; q < 14; q++) { a0[q] = B2[q]; a1[q] = B2[q]; }
        #pragma unroll 1
        for (int c = 0; c < NI / 4; c++) {
            float4 x0 = __ldg(r0 + c), x1 = __ldg(r1 + c);
            acc2(a0, a1, x0.x, x1.x, W + (4 * c + 0) * PW);
            acc2(a0, a1, x0.y, x1.y, W + (4 * c + 1) * PW);
            acc2(a0, a1, x0.z, x1.z, W + (4 * c + 2) * PW);
            acc2(a0, a1, x0.w, x1.w, W + (4 * c + 3) * PW);
        }
        float* dp = (pass ? g_right : g_left);
        float* o0 = dp + (size_t)n0 * PW + co;
        float* o1 = dp + (size_t)n1 * PW + co;
        #pragma unroll
        for (int q = 0; q < 7; q++) {
            ulonglong2 u; u.x = a0[2 * q]; u.y = a0[2 * q + 1];
            reinterpret_cast<ulonglong2*>(o0)[q] = u;
            ulonglong2 v; v.x = a1[2 * q]; v.y = a1[2 * q + 1];
            reinterpret_cast<ulonglong2*>(o1)[q] = v;
        }
    }
}

// ---------------------------------------------------------------------------
// Kernel 2: edge pass (persistent). thread: edges e0,e1 ; columns [half]
// ---------------------------------------------------------------------------
__global__ void __launch_bounds__(NTE, 1) k_edge(
    const float* __restrict__ ef, const int* __restrict__ srcp, const int* __restrict__ dstp,
    const float* __restrict__ w_e2n, const float* __restrict__ b_e2n,
    const float* __restrict__ w_e2e, const float* __restrict__ b_e2e,
    const float* __restrict__ w_u,  const float* __restrict__ b_u,
    float* __restrict__ out_edge)
{
    extern __shared__ float sm[];
    float* s_ef  = sm;                   // EB*53  (reused to hold relu(third))
    float* s_w2n = s_ef + EB * EFW;      // 50*56
    float* s_w2e = s_w2n + H * PW;       // 50*56
    float* s_wu  = s_w2e + H * PW;       // 156*56 (150 real + 6 zero rows)
    float* s_b2n = s_wu + 156 * PW;      // 56
    float* s_b2e = s_b2n + PW;           // 56
    float* s_bu  = s_b2e + PW;           // 56
    int*   s_src = reinterpret_cast<int*>(s_bu + PW);   // EB
    int*   s_dst = s_src + EB;                          // EB

    const int t = threadIdx.x;
    stage_w(s_w2n, w_e2n, H, H, t, NTE);
    stage_w(s_w2e, w_e2e, H, H, t, NTE);
    stage_w(s_wu,  w_u, 150, 156, t, NTE);
    stage_b(s_b2n, b_e2n, t);
    stage_b(s_b2e, b_e2e, t);
    stage_b(s_bu,  b_u,  t);

    const int half = t & 1;
    const int co   = half * HF;
    const int e0   = 2 * (t >> 1);
    const int e1   = e0 + 1;

    const int ntiles = E_N / EB;   // 3125 exact
    #pragma unroll 1
    for (int tile = blockIdx.x; tile < ntiles; tile += gridDim.x) {
        const int base = tile * EB;
        __syncthreads();                       // prev tile fully consumed
        #pragma unroll 1
        for (int i = t; i < EB * H; i += NTE)
            s_ef[(i / H) * EFW + (i % H)] = ef[(size_t)base * H + i];
        s_src[t] = srcp[base + t];
        s_dst[t] = dstp[base + t];
        __syncthreads();

        const float* f0 = s_ef + e0 * EFW;
        const float* f1 = s_ef + e1 * EFW;
        const int s0 = s_src[e0], s1 = s_src[e1];
        const int d0 = s_dst[e0], d1 = s_dst[e1];

        // ---- phase 1: e2n message (my half) -> relu -> red.v4 scatter
        {
            u64 a0[14], a1[14];
            const u64* B2 = reinterpret_cast<const u64*>(s_b2n + co);
            #pragma unroll
            for (int q = 0; q < 14; q++) { a0[q] = B2[q]; a1[q] = B2[q]; }
            const float* W = s_w2n + co;
            #pragma unroll 2
            for (int i = 0; i < H; i++)
                acc2(a0, a1, f0[i], f1[i], W + i * PW);
            float* A0 = g_acc + (size_t)d0 * PW + co;
            float* A1 = g_acc + (size_t)d1 * PW + co;
            #pragma unroll
            for (int c = 0; c < 7; c++) {
                float2 p = up2(a0[2 * c]), q2 = up2(a0[2 * c + 1]);
                red4(A0 + 4 * c, relu_f(p.x), relu_f(p.y), relu_f(q2.x), relu_f(q2.y));
            }
            #pragma unroll
            for (int c = 0; c < 7; c++) {
                float2 p = up2(a1[2 * c]), q2 = up2(a1[2 * c + 1]);
                red4(A1 + 4 * c, relu_f(p.x), relu_f(p.y), relu_f(q2.x), relu_f(q2.y));
            }
        }

        // ---- phase 2: third = relu(ef @ w_e2e + b) (my half) into regs
        u64 t0[14], t1[14];
        {
            const u64* B2 = reinterpret_cast<const u64*>(s_b2e + co);
            #pragma unroll
            for (int q = 0; q < 14; q++) { t0[q] = B2[q]; t1[q] = B2[q]; }
            const float* W = s_w2e + co;
            #pragma unroll 2
            for (int i = 0; i < H; i++)
                acc2(t0, t1, f0[i], f1[i], W + i * PW);
        }
        __syncthreads();   // everyone done reading f -> safe to overwrite s_ef
        {
            float* T0 = s_ef + e0 * EFW;
            float* T1 = s_ef + e1 * EFW;
            #pragma unroll
            for (int q = 0; q < 14; q++) {
                int c = co + 2 * q;
                float2 p = up2(t0[q]), r = up2(t1[q]);
                if (c < H)     { T0[c] = relu_f(p.x);     T1[c] = relu_f(r.x); }
                if (c + 1 < H) { T0[c + 1] = relu_f(p.y); T1[c + 1] = relu_f(r.y); }
            }
        }
        __syncthreads();

        // ---- phase 3: new_edge (my half) = bias + folds
        u64 o0[14], o1[14];
        {
            const u64* B2 = reinterpret_cast<const u64*>(s_bu + co);
            #pragma unroll
            for (int q = 0; q < 14; q++) { o0[q] = B2[q]; o1[q] = B2[q]; }
        }
        // fold third (w_u rows 100..149), x from exchanged smem
        {
            const float* W = s_wu + 100 * PW + co;
            const float* T0 = s_ef + e0 * EFW;
            const float* T1 = s_ef + e1 * EFW;
            #pragma unroll 2
            for (int r = 0; r < H; r++)
                acc2(o0, o1, T0[r], T1[r], W + r * PW);
        }
        // fold first = relu(left[src]+right[dst]) (w_u rows 0..55, pads x=0)
        {
            const float4* La0 = reinterpret_cast<const float4*>(g_left  + (size_t)s0 * PW);
            const float4* Rb0 = reinterpret_cast<const float4*>(g_right + (size_t)d0 * PW);
            const float4* La1 = reinterpret_cast<const float4*>(g_left  + (size_t)s1 * PW);
            const float4* Rb1 = reinterpret_cast<const float4*>(g_right + (size_t)d1 * PW);
            const float* W = s_wu + co;
            #pragma unroll 1
            for (int c = 0; c < 14; c++) {
                float4 a0 = __ldg(La0 + c), b0 = __ldg(Rb0 + c);
                float4 a1 = __ldg(La1 + c), b1 = __ldg(Rb1 + c);
                acc2(o0, o1, relu_f(a0.x + b0.x), relu_f(a1.x + b1.x), W + (4 * c + 0) * PW);
                acc2(o0, o1, relu_f(a0.y + b0.y), relu_f(a1.y + b1.y), W + (4 * c + 1) * PW);
                acc2(o0, o1, relu_f(a0.z + b0.z), relu_f(a1.z + b1.z), W + (4 * c + 2) * PW);
                acc2(o0, o1, relu_f(a0.w + b0.w), relu_f(a1.w + b1.w), W + (4 * c + 3) * PW);
            }
        }
        // fold second = relu(right[src]+left[dst]) (w_u rows 50..105, pads x=0)
        {
            const float4* Ra0 = reinterpret_cast<const float4*>(g_right + (size_t)s0 * PW);
            const float4* Lb0 = reinterpret_cast<const float4*>(g_left  + (size_t)d0 * PW);
            const float4* Ra1 = reinterpret_cast<const float4*>(g_right + (size_t)s1 * PW);
            const float4* Lb1 = reinterpret_cast<const float4*>(g_left  + (size_t)d1 * PW);
            const float* W = s_wu + 50 * PW + co;
            #pragma unroll 1
            for (int c = 0; c < 14; c++) {
                float4 a0 = __ldg(Ra0 + c), b0 = __ldg(Lb0 + c);
                float4 a1 = __ldg(Ra1 + c), b1 = __ldg(Lb1 + c);
                acc2(o0, o1, relu_f(a0.x + b0.x), relu_f(a1.x + b1.x), W + (4 * c + 0) * PW);
                acc2(o0, o1, relu_f(a0.y + b0.y), relu_f(a1.y + b1.y), W + (4 * c + 1) * PW);
                acc2(o0, o1, relu_f(a0.z + b0.z), relu_f(a1.z + b1.z), W + (4 * c + 2) * PW);
                acc2(o0, o1, relu_f(a0.w + b0.w), relu_f(a1.w + b1.w), W + (4 * c + 3) * PW);
            }
        }

        // store my half (cols co..co+27, clipped to 50), float2-aligned
        {
            float* O0 = out_edge + (size_t)(base + e0) * H + co;
            float* O1 = out_edge + (size_t)(base + e1) * H + co;
            const int QN = half ? 11 : 14;   // half1: cols 28..49 = 11 pairs
            #pragma unroll
            for (int q = 0; q < 14; q++) {
                if (q < QN) {
                    float2 p = up2(o0[q]);
                    reinterpret_cast<float2*>(O0)[q] = make_float2(relu_f(p.x), relu_f(p.y));
                    float2 r = up2(o1[q]);
                    reinterpret_cast<float2*>(O1)[q] = make_float2(relu_f(r.x), relu_f(r.y));
                }
            }
        }
    }
}

// ---------------------------------------------------------------------------
// Kernel 3: new_node. thread: nodes n0,n1 ; columns [half]
// ---------------------------------------------------------------------------
__global__ void __launch_bounds__(NT) k_node_final(
    const float* __restrict__ nf,
    const float* __restrict__ w_n2n, const float* __restrict__ b_n2n,
    const float* __restrict__ w_u,   const float* __restrict__ b_u,
    float* __restrict__ out_node)
{
    extern __shared__ float sm[];
    float* s_nn = sm;                    // 256*53 exchanged node_node
    float* s_wn = s_nn + NT * EFW;       // 128*56
    float* s_wu = s_wn + NI * PW;        // 106*56 (100 real + 6 zero)
    float* s_bn = s_wu + 106 * PW;       // 56
    float* s_bu = s_bn + PW;             // 56
    stage_w(s_wn, w_n2n, NI, NI, threadIdx.x, NT);
    stage_w(s_wu, w_u, 100, 106, threadIdx.x, NT);
    stage_b(s_bn, b_n2n, threadIdx.x);
    stage_b(s_bu, b_u, threadIdx.x);
    __syncthreads();

    const int half = threadIdx.x & 1;
    const int co   = half * HF;
    const int lp   = 2 * (threadIdx.x >> 1);          // local node pair base
    const int n0   = blockIdx.x * NT + lp;
    const int n1   = n0 + 1;
    const bool ok  = (n0 < V_N);

    // phase 1: node_node (my half) -> relu -> exchange via s_nn
    if (ok) {
        const float4* r0 = reinterpret_cast<const float4*>(nf + (size_t)n0 * NI);
        const float4* r1 = reinterpret_cast<const float4*>(nf + (size_t)n1 * NI);
        u64 a0[14], a1[14];
        const u64* B2 = reinterpret_cast<const u64*>(s_bn + co);
        #pragma unroll
        for (int q = 0; q < 14; q++) { a0[q] = B2[q]; a1[q] = B2[q]; }
        const float* W = s_wn + co;
        #pragma unroll 1
        for (int c = 0; c < NI / 4; c++) {
            float4 x0 = __ldg(r0 + c), x1 = __ldg(r1 + c);
            acc2(a0, a1, x0.x, x1.x, W + (4 * c + 0) * PW);
            acc2(a0, a1, x0.y, x1.y, W + (4 * c + 1) * PW);
            acc2(a0, a1, x0.z, x1.z, W + (4 * c + 2) * PW);
            acc2(a0, a1, x0.w, x1.w, W + (4 * c + 3) * PW);
        }
        float* T0 = s_nn + lp * EFW;
        float* T1 = T0 + EFW;
        #pragma unroll
        for (int q = 0; q < 14; q++) {
            int c = co + 2 * q;
            float2 p = up2(a0[q]), r = up2(a1[q]);
            if (c < H)     { T0[c] = relu_f(p.x);     T1[c] = relu_f(r.x); }
            if (c + 1 < H) { T0[c + 1] = relu_f(p.y); T1[c + 1] = relu_f(r.y); }
        }
    }
    __syncthreads();
    if (!ok) return;

    // phase 2: fold
    u64 o0[14], o1[14];
    {
        const u64* B2 = reinterpret_cast<const u64*>(s_bu + co);
        #pragma unroll
        for (int q = 0; q < 14; q++) { o0[q] = B2[q]; o1[q] = B2[q]; }
    }
    {   // node_node through w_u rows 0..49
        const float* W = s_wu + co;
        const float* T0 = s_nn + lp * EFW;
        const float* T1 = T0 + EFW;
        #pragma unroll 2
        for (int r = 0; r < H; r++)
            acc2(o0, o1, T0[r], T1[r], W + r * PW);
    }
    {   // edge_node (g_acc, raw) through w_u rows 50..105 (pads x=0)
        const float4* A0 = reinterpret_cast<const float4*>(g_acc + (size_t)n0 * PW);
        const float4* A1 = reinterpret_cast<const float4*>(g_acc + (size_t)n1 * PW);
        const float* W = s_wu + 50 * PW + co;
        #pragma unroll 1
        for (int c = 0; c < 14; c++) {
            float4 a0 = __ldg(A0 + c), a1 = __ldg(A1 + c);
            acc2(o0, o1, a0.x, a1.x, W + (4 * c + 0) * PW);
            acc2(o0, o1, a0.y, a1.y, W + (4 * c + 1) * PW);
            acc2(o0, o1, a0.z, a1.z, W + (4 * c + 2) * PW);
            acc2(o0, o1, a0.w, a1.w, W + (4 * c + 3) * PW);
        }
    }
    {
        float* O0 = out_node + (size_t)n0 * H + co;
        float* O1 = out_node + (size_t)n1 * H + co;
        const int QN = half ? 11 : 14;
        #pragma unroll
        for (int q = 0; q < 14; q++) {
            if (q < QN) {
                float2 p = up2(o0[q]);
                reinterpret_cast<float2*>(O0)[q] = make_float2(relu_f(p.x), relu_f(p.y));
                float2 r = up2(o1[q]);
                reinterpret_cast<float2*>(O1)[q] = make_float2(relu_f(r.x), relu_f(r.y));
            }
        }
    }
}

// ---------------------------------------------------------------------------
extern "C" void kernel_launch(void* const* d_in, const int* in_sizes, int n_in,
                              void* d_out, int out_size) {
    const float* nf    = (const float*)d_in[0];
    const float* ef    = (const float*)d_in[1];
    const int*   srcp  = (const int*)d_in[2];
    const int*   dstp  = (const int*)d_in[3];
    const float* w_n2n = (const float*)d_in[4];  const float* b_n2n = (const float*)d_in[5];
    const float* w_e2n = (const float*)d_in[6];  const float* b_e2n = (const float*)d_in[7];
    const float* w_upn = (const float*)d_in[8];  const float* b_upn = (const float*)d_in[9];
    const float* w_l   = (const float*)d_in[10]; const float* b_l   = (const float*)d_in[11];
    const float* w_r   = (const float*)d_in[12]; const float* b_r   = (const float*)d_in[13];
    const float* w_e2e = (const float*)d_in[14]; const float* b_e2e = (const float*)d_in[15];
    const float* w_upe = (const float*)d_in[16]; const float* b_upe = (const float*)d_in[17];

    float* out_node = (float*)d_out;
    float* out_edge = out_node + (size_t)V_N * H;

    size_t sm_lr   = (size_t)(2 * NI * PW + 2 * PW) * 4;
    size_t sm_edge = (size_t)(EB * EFW + (50 + 50 + 156) * PW + 3 * PW) * 4 + 2 * EB * 4;
    size_t sm_fin  = (size_t)(NT * EFW + NI * PW + 106 * PW + 2 * PW) * 4;

    cudaFuncSetAttribute(k_node_lr,    cudaFuncAttributeMaxDynamicSharedMemorySize, (int)sm_lr);
    cudaFuncSetAttribute(k_edge,       cudaFuncAttributeMaxDynamicSharedMemorySize, (int)sm_edge);
    cudaFuncSetAttribute(k_node_final, cudaFuncAttributeMaxDynamicSharedMemorySize, (int)sm_fin);

    int nblk = (V_N + NT - 1) / NT;   // 391
    k_node_lr<<<nblk, NT, sm_lr>>>(nf, w_l, b_l, w_r, b_r);
    k_edge<<<148, NTE, sm_edge>>>(ef, srcp, dstp, w_e2n, b_e2n, w_e2e, b_e2e,
                                  w_upe, b_upe, out_edge);
    k_node_final<<<nblk, NT, sm_fin>>>(nf, w_n2n, b_n2n, w_upn, b_upn, out_node);
}